// round 1
// baseline (speedup 1.0000x reference)
#include <cuda_runtime.h>

#define NB 8
#define ND 1024
#define NT 512
#define NHID 256
#define NHEAD 4
#define NLAY 2
#define NOUT 64
#define MR (NB*ND)          // 8192 rows
#define NBH (NB*NHEAD)      // 32 batch-heads
#define ALPHA_F 0.2f
#define EPS_F 1e-5f

// ---------------- scratch (device globals; no runtime allocation) ----------------
__device__ float g_posmean[ND*NT];
__device__ float g_xcat[MR*(2*NT)];
__device__ float g_h[MR*NHID];
__device__ float g_hW[MR*NHID];
__device__ float g_Wcat[NHID*NHID];
__device__ float g_sl[NBH*ND];
__device__ float g_sr[NBH*ND];
__device__ float g_skey[NBH*ND];
__device__ int   g_sidx[NBH*ND];
__device__ float g_whi[NBH*ND];
__device__ float g_wlo[NBH*ND];
__device__ float g_zhi[NBH*(ND+1)];
__device__ float g_zlo[NBH*(ND+1)];
__device__ float g_suf[NBH*(ND+1)*NOUT];   // [bh][k][e]  suffix sums of exp(s_r)*hW
__device__ float g_pref[NBH*(ND+1)*NOUT];  // [bh][k][e]  prefix sums of exp(a*s_r)*hW
__device__ float g_hout[MR*NHID];

// ---------------- elementwise front ----------------
__global__ void posmean_kernel(const float* __restrict__ X, const float* __restrict__ Mk) {
    int i = blockIdx.x * 256 + threadIdx.x;            // i < ND*NT
    float s = 0.f, c = 0.f;
    #pragma unroll
    for (int b = 0; b < NB; b++) {
        float m = Mk[b*ND*NT + i];
        s += X[b*ND*NT + i] * m;
        c += m;
    }
    g_posmean[i] = s / (c + 1e-10f);
}

__global__ void xcat_kernel(const float* __restrict__ X, const float* __restrict__ Mk) {
    int i = blockIdx.x * 256 + threadIdx.x;            // i < NB*ND*NT
    int r = i / NT;
    int t = i - r * NT;
    int p = i % (ND*NT);
    float m = Mk[i];
    float x = X[i];
    float pm = g_posmean[p];
    g_xcat[r*(2*NT) + t]      = x*m + (1.f - m)*pm;
    g_xcat[r*(2*NT) + NT + t] = m;
}

// ---------------- SGEMM: C[M,N] = A[M,K] @ B[K,N] (+bias) ----------------
#define BM 128
#define BN 64
#define BKG 16
__global__ __launch_bounds__(256) void sgemm_kernel(
    int M, int N, int K,
    const float* __restrict__ A, const float* __restrict__ Bm,
    const float* __restrict__ bias, float* __restrict__ C)
{
    __shared__ float As[BKG][BM];
    __shared__ float Bs[BKG][BN];
    int tid = threadIdx.x;
    int tx = tid & 15;     // 16 col-groups of 4
    int ty = tid >> 4;     // 16 row-groups of 8
    int m0 = blockIdx.y * BM, n0 = blockIdx.x * BN;

    float acc[8][4];
    #pragma unroll
    for (int i = 0; i < 8; i++)
        #pragma unroll
        for (int j = 0; j < 4; j++) acc[i][j] = 0.f;

    float bb[4] = {0.f, 0.f, 0.f, 0.f};
    if (bias) {
        #pragma unroll
        for (int j = 0; j < 4; j++) bb[j] = bias[n0 + tx*4 + j];
    }

    for (int kt = 0; kt < K; kt += BKG) {
        #pragma unroll
        for (int i = 0; i < 2; i++) {
            int id = tid + i*256;                // 512 float4 loads for A tile
            int r = id >> 2;
            int c4 = (id & 3) << 2;
            float4 v = *(const float4*)&A[(size_t)(m0 + r)*K + kt + c4];
            As[c4+0][r] = v.x; As[c4+1][r] = v.y; As[c4+2][r] = v.z; As[c4+3][r] = v.w;
        }
        {
            int r = tid >> 4;
            int c = (tid & 15) << 2;
            float4 v = *(const float4*)&Bm[(size_t)(kt + r)*N + n0 + c];
            *(float4*)&Bs[r][c] = v;
        }
        __syncthreads();
        #pragma unroll
        for (int kk = 0; kk < BKG; kk++) {
            float4 a0 = *(float4*)&As[kk][ty*8];
            float4 a1 = *(float4*)&As[kk][ty*8 + 4];
            float4 bq = *(float4*)&Bs[kk][tx*4];
            float a[8] = {a0.x, a0.y, a0.z, a0.w, a1.x, a1.y, a1.z, a1.w};
            float bvv[4] = {bq.x, bq.y, bq.z, bq.w};
            #pragma unroll
            for (int i = 0; i < 8; i++)
                #pragma unroll
                for (int j = 0; j < 4; j++) acc[i][j] += a[i] * bvv[j];
        }
        __syncthreads();
    }

    #pragma unroll
    for (int i = 0; i < 8; i++) {
        int row = m0 + ty*8 + i;
        float4 o;
        o.x = acc[i][0] + bb[0];
        o.y = acc[i][1] + bb[1];
        o.z = acc[i][2] + bb[2];
        o.w = acc[i][3] + bb[3];
        *(float4*)&C[(size_t)row*N + n0 + tx*4] = o;
    }
}

// ---------------- pack gat_W[l] (NH,HID,OUT) -> (HID, NH*OUT) ----------------
__global__ void wcat_kernel(const float* __restrict__ gat_W, int l) {
    int i = blockIdx.x * 256 + threadIdx.x;   // i < HID*HID
    int k = i >> 8;             // /NHID
    int c = i & 255;
    int h = c >> 6;             // /NOUT
    int e = c & 63;
    g_Wcat[i] = gat_W[((l*NHEAD + h)*NHID + k)*NOUT + e];
}

// ---------------- s_l, s_r ----------------
__global__ void s_kernel(const float* __restrict__ gat_a, int l) {
    int t = blockIdx.x * 256 + threadIdx.x;   // t < MR*NHEAD
    int row = t >> 2;
    int h = t & 3;
    int b = row / ND, n = row - b*ND;
    const float* hw = &g_hW[row*NHID + h*NOUT];
    const float* al = &gat_a[(l*NHEAD + h)*2*NOUT];
    float sl = 0.f, sr = 0.f;
    #pragma unroll 8
    for (int e = 0; e < NOUT; e++) {
        float v = hw[e];
        sl += v * al[e];
        sr += v * al[NOUT + e];
    }
    int bh = b*NHEAD + h;
    g_sl[bh*ND + n] = sl;
    g_sr[bh*ND + n] = sr;
}

// ---------------- block-wide inclusive scan (1024 threads) ----------------
__device__ __forceinline__ float warp_incl_scan(float v) {
    int lane = threadIdx.x & 31;
    #pragma unroll
    for (int o = 1; o < 32; o <<= 1) {
        float t = __shfl_up_sync(0xffffffffu, v, o);
        if (lane >= o) v += t;
    }
    return v;
}
__device__ float block_incl_scan_1024(float v, float* ws) {
    __syncthreads();                           // protect ws reuse across calls
    int lane = threadIdx.x & 31, w = threadIdx.x >> 5;
    v = warp_incl_scan(v);
    if (lane == 31) ws[w] = v;
    __syncthreads();
    if (w == 0) {
        float x = ws[lane];
        x = warp_incl_scan(x);
        ws[lane] = x;
    }
    __syncthreads();
    if (w > 0) v += ws[w - 1];
    return v;
}

// ---------------- sort s_r per (b,h), exp weights, scalar Z scans ----------------
__global__ __launch_bounds__(1024) void prep_sort_kernel() {
    __shared__ float key[1024];
    __shared__ int   sidx[1024];
    __shared__ float ws[32];
    int bh = blockIdx.x, tid = threadIdx.x;
    key[tid] = g_sr[bh*ND + tid];
    sidx[tid] = tid;
    __syncthreads();
    for (int k = 2; k <= 1024; k <<= 1) {
        for (int j = k >> 1; j > 0; j >>= 1) {
            int ixj = tid ^ j;
            if (ixj > tid) {
                float a = key[tid], c = key[ixj];
                bool asc = (tid & k) == 0;
                if (asc ? (a > c) : (a < c)) {
                    key[tid] = c; key[ixj] = a;
                    int t = sidx[tid]; sidx[tid] = sidx[ixj]; sidx[ixj] = t;
                }
            }
            __syncthreads();
        }
    }
    float kv = key[tid];
    float whi = __expf(kv);
    float wlo = __expf(ALPHA_F * kv);
    int gb = bh*ND + tid;
    g_skey[gb] = kv;
    g_sidx[gb] = sidx[tid];
    g_whi[gb] = whi;
    g_wlo[gb] = wlo;

    float Ilo = block_incl_scan_1024(wlo, ws);
    g_zlo[bh*(ND+1) + tid + 1] = Ilo;

    float kr = key[1023 - tid];                // direct reverse scan for suffix (positive sums)
    float whr = __expf(kr);
    float Ir = block_incl_scan_1024(whr, ws);
    g_zhi[bh*(ND+1) + (1023 - tid)] = Ir;
    if (tid == 0) {
        g_zlo[bh*(ND+1)] = 0.f;
        g_zhi[bh*(ND+1) + ND] = 0.f;
    }
}

// ---------------- vector prefix/suffix sums of weighted hW: one block per (e, bh) ----------------
__global__ __launch_bounds__(1024) void prep_scan_kernel() {
    __shared__ float ws[32];
    __shared__ float tot_s;
    int e = blockIdx.x, bh = blockIdx.y, tid = threadIdx.x;
    int b = bh >> 2, h = bh & 3;
    int m = g_sidx[bh*ND + tid];
    float hv = g_hW[(b*ND + m)*NHID + h*NOUT + e];
    float vlo = g_wlo[bh*ND + tid] * hv;
    float vhi = g_whi[bh*ND + tid] * hv;

    float Ilo = block_incl_scan_1024(vlo, ws);
    float Ihi = block_incl_scan_1024(vhi, ws);
    if (tid == 1023) tot_s = Ihi;
    __syncthreads();
    float Tot = tot_s;

    int base = bh*(ND+1)*NOUT + e;
    g_pref[base + (tid + 1)*NOUT] = Ilo;
    g_suf[base + tid*NOUT] = Tot - (Ihi - vhi);  // suffix from k=tid (error ~2^-24 * |Tot|, fine)
    if (tid == 0) {
        g_pref[base] = 0.f;
        g_suf[base + ND*NOUT] = 0.f;
    }
}

// ---------------- per-row attention output via binary search ----------------
__global__ __launch_bounds__(256) void attn_apply_kernel() {
    __shared__ float skey_s[1024];
    int bh = blockIdx.y;
    int b = bh >> 2, h = bh & 3;
    int tid = threadIdx.x;
    int warp = tid >> 5, lane = tid & 31;
    for (int i = tid; i < 1024; i += 256) skey_s[i] = g_skey[bh*ND + i];
    __syncthreads();
    int nbase = blockIdx.x * 128 + warp * 16;
    for (int it = 0; it < 16; it++) {
        int n = nbase + it;
        float sl = g_sl[bh*ND + n];
        float thr = -sl;
        int lo = 0, hi = 1024;
        while (lo < hi) {                       // first k with skey[k] > thr
            int mid = (lo + hi) >> 1;
            if (skey_s[mid] > thr) hi = mid; else lo = mid + 1;
        }
        int k = lo;
        float esl = __expf(sl);
        float eal = __expf(ALPHA_F * sl);
        float Z = esl * g_zhi[bh*(ND+1) + k] + eal * g_zlo[bh*(ND+1) + k];
        float invZ = 1.0f / Z;
        const float* suf = &g_suf[(bh*(ND+1) + k)*NOUT];
        const float* pre = &g_pref[(bh*(ND+1) + k)*NOUT];
        float v0 = (esl * suf[lane]      + eal * pre[lane])      * invZ;
        float v1 = (esl * suf[lane + 32] + eal * pre[lane + 32]) * invZ;
        int orow = (b*ND + n)*NHID + h*NOUT;
        g_hout[orow + lane] = v0;
        g_hout[orow + lane + 32] = v1;
    }
}

// ---------------- residual + layernorm (in place on g_h) ----------------
__device__ float block_sum_256(float v, float* ws) {
    __syncthreads();
    int lane = threadIdx.x & 31, w = threadIdx.x >> 5;
    #pragma unroll
    for (int o = 16; o > 0; o >>= 1) v += __shfl_xor_sync(0xffffffffu, v, o);
    if (lane == 0) ws[w] = v;
    __syncthreads();
    if (threadIdx.x == 0) {
        float s = 0.f;
        #pragma unroll
        for (int i = 0; i < 8; i++) s += ws[i];
        ws[8] = s;
    }
    __syncthreads();
    return ws[8];
}

__global__ __launch_bounds__(256) void ln_kernel(const float* __restrict__ ln_g,
                                                 const float* __restrict__ ln_b, int l) {
    __shared__ float ws[9];
    int row = blockIdx.x, tid = threadIdx.x;
    float v = g_h[row*NHID + tid] + g_hout[row*NHID + tid];
    float mu = block_sum_256(v, ws) * (1.0f / NHID);
    float d = v - mu;
    float var = block_sum_256(d*d, ws) * (1.0f / NHID);
    g_h[row*NHID + tid] = d * rsqrtf(var + EPS_F) * ln_g[l*NHID + tid] + ln_b[l*NHID + tid];
}

// ---------------- launch ----------------
extern "C" void kernel_launch(void* const* d_in, const int* in_sizes, int n_in,
                              void* d_out, int out_size) {
    const float* X     = (const float*)d_in[0];
    const float* Mk    = (const float*)d_in[1];
    const float* W_in  = (const float*)d_in[2];
    const float* b_in  = (const float*)d_in[3];
    const float* gat_W = (const float*)d_in[4];
    const float* gat_a = (const float*)d_in[5];
    const float* ln_g  = (const float*)d_in[6];
    const float* ln_b  = (const float*)d_in[7];
    const float* W_out = (const float*)d_in[8];
    const float* b_out = (const float*)d_in[9];
    float* out = (float*)d_out;

    float *p_xcat, *p_h, *p_hW, *p_Wcat;
    cudaGetSymbolAddress((void**)&p_xcat, g_xcat);
    cudaGetSymbolAddress((void**)&p_h,    g_h);
    cudaGetSymbolAddress((void**)&p_hW,   g_hW);
    cudaGetSymbolAddress((void**)&p_Wcat, g_Wcat);

    posmean_kernel<<<(ND*NT)/256, 256>>>(X, Mk);
    xcat_kernel<<<(NB*ND*NT)/256, 256>>>(X, Mk);

    // h = xcat @ W_in + b_in
    sgemm_kernel<<<dim3(NHID/BN, MR/BM), 256>>>(MR, NHID, 2*NT, p_xcat, W_in, b_in, p_h);

    for (int l = 0; l < NLAY; l++) {
        wcat_kernel<<<(NHID*NHID)/256, 256>>>(gat_W, l);
        // hW = h @ Wcat
        sgemm_kernel<<<dim3(NHID/BN, MR/BM), 256>>>(MR, NHID, NHID, p_h, p_Wcat, nullptr, p_hW);
        s_kernel<<<(MR*NHEAD)/256, 256>>>(gat_a, l);
        prep_sort_kernel<<<NBH, 1024>>>();
        prep_scan_kernel<<<dim3(NOUT, NBH), 1024>>>();
        attn_apply_kernel<<<dim3(ND/128, NBH), 256>>>();
        ln_kernel<<<MR, 256>>>(ln_g, ln_b, l);
    }

    // out = h @ W_out + b_out
    sgemm_kernel<<<dim3(NT/BN, MR/BM), 256>>>(MR, NT, NHID, p_h, W_out, b_out, out);
}

// round 15
// speedup vs baseline: 1.3694x; 1.3694x over previous
#include <cuda_runtime.h>
#include <cuda_bf16.h>
#include <cstdint>

#define NB 8
#define ND 1024
#define NT 512
#define NHID 256
#define NHEAD 4
#define NLAY 2
#define NOUT 64
#define MR (NB*ND)          // 8192 rows
#define NBH (NB*NHEAD)      // 32 batch-heads
#define ALPHA_F 0.2f
#define EPS_F 1e-5f

#define SMEM_SWIZZLE_128B(b) ((b) ^ (((b) >> 3) & 0x70))

__device__ __forceinline__ uint32_t smem_to_u32(const void* p) {
    uint32_t a;
    asm("{ .reg .u64 t; cvta.to.shared.u64 t, %1; cvt.u32.u64 %0, t; }" : "=r"(a) : "l"(p));
    return a;
}
__device__ __forceinline__ void ldsm_x4(uint32_t* r, uint32_t addr) {
    asm volatile("ldmatrix.sync.aligned.m8n8.x4.shared.b16 {%0,%1,%2,%3}, [%4];"
        : "=r"(r[0]), "=r"(r[1]), "=r"(r[2]), "=r"(r[3]) : "r"(addr));
}
__device__ __forceinline__ void ldsm_x2(uint32_t* r, uint32_t addr) {
    asm volatile("ldmatrix.sync.aligned.m8n8.x2.shared.b16 {%0,%1}, [%2];"
        : "=r"(r[0]), "=r"(r[1]) : "r"(addr));
}
__device__ __forceinline__ void mma16816(float* c, const uint32_t* a, const uint32_t* b) {
    asm volatile("mma.sync.aligned.m16n8k16.row.col.f32.bf16.bf16.f32 "
        "{%0,%1,%2,%3}, {%4,%5,%6,%7}, {%8,%9}, {%0,%1,%2,%3};"
        : "+f"(c[0]), "+f"(c[1]), "+f"(c[2]), "+f"(c[3])
        : "r"(a[0]), "r"(a[1]), "r"(a[2]), "r"(a[3]), "r"(b[0]), "r"(b[1]));
}

// ================= scratch =================
__device__ float g_posmean[ND*NT];
__device__ __nv_bfloat16 g_Axh[MR*(2*NT)];
__device__ __nv_bfloat16 g_Axl[MR*(2*NT)];
__device__ __nv_bfloat16 g_WinTh[NHID*(2*NT)];
__device__ __nv_bfloat16 g_WinTl[NHID*(2*NT)];
__device__ __nv_bfloat16 g_WcatTh[NHID*NHID];
__device__ __nv_bfloat16 g_WcatTl[NHID*NHID];
__device__ __nv_bfloat16 g_WoutTh[NT*NHID];
__device__ __nv_bfloat16 g_WoutTl[NT*NHID];
__device__ float g_h[MR*NHID];
__device__ __nv_bfloat16 g_hh[MR*NHID];
__device__ __nv_bfloat16 g_hl[MR*NHID];
__device__ float g_hW[MR*NHID];
__device__ float g_sl[NBH*ND];
__device__ float g_sr[NBH*ND];
__device__ float g_skey[NBH*ND];
__device__ int   g_sidx[NBH*ND];
__device__ float g_whi[NBH*ND];
__device__ float g_wlo[NBH*ND];
__device__ float g_zhi[NBH*(ND+1)];
__device__ float g_zlo[NBH*(ND+1)];
__device__ float g_suf[NBH*(ND+1)*NOUT];
__device__ float g_pref[NBH*(ND+1)*NOUT];
__device__ float g_hout[MR*NHID];

// ================= elementwise front =================
__global__ void posmean_kernel(const float* __restrict__ X, const float* __restrict__ Mk) {
    int i = blockIdx.x * 256 + threadIdx.x;
    float s = 0.f, c = 0.f;
    #pragma unroll
    for (int b = 0; b < NB; b++) {
        float m = Mk[b*ND*NT + i];
        s += X[b*ND*NT + i] * m;
        c += m;
    }
    g_posmean[i] = s / (c + 1e-10f);
}

__global__ void xcat_bf16_kernel(const float* __restrict__ X, const float* __restrict__ Mk) {
    int i = blockIdx.x * 256 + threadIdx.x;            // i < NB*ND*NT
    int r = i / NT;
    int t = i - r * NT;
    int p = i % (ND*NT);
    float m = Mk[i];
    float x = X[i];
    float pm = g_posmean[p];
    float xm = x*m + (1.f - m)*pm;
    __nv_bfloat16 hi = __float2bfloat16(xm);
    __nv_bfloat16 lo = __float2bfloat16(xm - __bfloat162float(hi));
    size_t base = (size_t)r * (2*NT);
    g_Axh[base + t] = hi;
    g_Axl[base + t] = lo;
    g_Axh[base + NT + t] = __float2bfloat16(m);   // 0/1 exact
    g_Axl[base + NT + t] = __float2bfloat16(0.f);
}

// ================= transpose + fp32->bf16 hi/lo split =================
__global__ void transconv_kernel(const float* __restrict__ src, int R, int C,
                                 __nv_bfloat16* __restrict__ dhi, __nv_bfloat16* __restrict__ dlo,
                                 int dld, int drows_per_batch, int sbatch) {
    __shared__ float t[32][33];
    const float* s = src + (size_t)blockIdx.z * sbatch;
    int r0 = blockIdx.y * 32, c0 = blockIdx.x * 32;
    int tx = threadIdx.x, ty = threadIdx.y;
    #pragma unroll
    for (int i = 0; i < 4; i++)
        t[ty + 8*i][tx] = s[(size_t)(r0 + ty + 8*i)*C + c0 + tx];
    __syncthreads();
    int drow0 = blockIdx.z * drows_per_batch;
    #pragma unroll
    for (int i = 0; i < 4; i++) {
        int c = ty + 8*i;
        float v = t[tx][c];
        __nv_bfloat16 hi = __float2bfloat16(v);
        __nv_bfloat16 lo = __float2bfloat16(v - __bfloat162float(hi));
        size_t o = (size_t)(drow0 + c0 + c)*dld + r0 + tx;
        dhi[o] = hi; dlo[o] = lo;
    }
}

// ================= bf16x3 HMMA GEMM =================
// C[M,N] = A[M,K] @ Bt[N,K]^T via 3 passes: Ahi*Bhi + Alo*Bhi + Ahi*Blo.
// CTA 128x128, 8 warps of 64x32, BK=64, mma.sync m16n8k16.
__global__ __launch_bounds__(256) void mma_gemm_kernel(
    int K, int lda, int ldb, int ldc,
    const __nv_bfloat16* __restrict__ Ahi, const __nv_bfloat16* __restrict__ Alo,
    const __nv_bfloat16* __restrict__ Bhi, const __nv_bfloat16* __restrict__ Blo,
    const float* __restrict__ bias, float* __restrict__ C,
    __nv_bfloat16* __restrict__ Chi, __nv_bfloat16* __restrict__ Clo)
{
    __shared__ __align__(1024) char sA[128*128];   // 128 rows x 128B (64 bf16)
    __shared__ __align__(1024) char sB[128*128];
    const int tid = threadIdx.x;
    const int w = tid >> 5, l = tid & 31;
    const int m0 = blockIdx.y * 128, n0 = blockIdx.x * 128;
    const int wm = w >> 2, wn = w & 3;       // warp tile: rows wm*64, cols wn*32
    const uint32_t aBase = smem_to_u32(sA);
    const uint32_t bBase = smem_to_u32(sB);

    float acc[4][4][4];
    #pragma unroll
    for (int i = 0; i < 4; i++)
        #pragma unroll
        for (int j = 0; j < 4; j++)
            #pragma unroll
            for (int q = 0; q < 4; q++) acc[i][j][q] = 0.f;

    const int rbase = w*16 + (l >> 3);       // each thread: 4 rows, 16B column chunk
    const int c16 = l & 7;
    const int kchunks = K >> 6;
    const int nch = 3 * kchunks;

    uint4 va[4], vb[4];
    {   // prefetch chunk 0 (pass 0: hi*hi)
        #pragma unroll
        for (int i = 0; i < 4; i++) {
            int row = rbase + i*4;
            va[i] = *(const uint4*)(Ahi + (size_t)(m0 + row)*lda + c16*8);
            vb[i] = *(const uint4*)(Bhi + (size_t)(n0 + row)*ldb + c16*8);
        }
    }

    for (int c = 0; c < nch; c++) {
        __syncthreads();   // previous compute done reading smem
        #pragma unroll
        for (int i = 0; i < 4; i++) {
            int row = rbase + i*4;
            *(uint4*)(sA + SMEM_SWIZZLE_128B(row*128 + c16*16)) = va[i];
            *(uint4*)(sB + SMEM_SWIZZLE_128B(row*128 + c16*16)) = vb[i];
        }
        __syncthreads();
        if (c + 1 < nch) {
            int p = (c + 1) / kchunks;
            int k0 = ((c + 1) - p * kchunks) << 6;
            const __nv_bfloat16* As = (p == 1) ? Alo : Ahi;
            const __nv_bfloat16* Bs = (p == 2) ? Blo : Bhi;
            #pragma unroll
            for (int i = 0; i < 4; i++) {
                int row = rbase + i*4;
                va[i] = *(const uint4*)(As + (size_t)(m0 + row)*lda + k0 + c16*8);
                vb[i] = *(const uint4*)(Bs + (size_t)(n0 + row)*ldb + k0 + c16*8);
            }
        }
        // compute this chunk: 4 k16-steps
        #pragma unroll
        for (int kk = 0; kk < 4; kk++) {
            uint32_t af[4][4], bf_[4][2];
            int arow = wm*64 + (l & 15);
            int akh = l >> 4;
            #pragma unroll
            for (int mt = 0; mt < 4; mt++)
                ldsm_x4(af[mt], aBase + SMEM_SWIZZLE_128B((arow + mt*16)*128 + kk*32 + akh*16));
            int brow = wn*32 + (l & 7);
            int bkh = (l >> 3) & 1;
            #pragma unroll
            for (int nt = 0; nt < 4; nt++)
                ldsm_x2(bf_[nt], bBase + SMEM_SWIZZLE_128B((brow + nt*8)*128 + kk*32 + bkh*16));
            #pragma unroll
            for (int mt = 0; mt < 4; mt++)
                #pragma unroll
                for (int nt = 0; nt < 4; nt++)
                    mma16816(acc[mt][nt], af[mt], bf_[nt]);
        }
    }

    // epilogue
    const int r0w = m0 + wm*64;
    const int c0w = n0 + wn*32;
    #pragma unroll
    for (int mt = 0; mt < 4; mt++) {
        #pragma unroll
        for (int nt = 0; nt < 4; nt++) {
            int col = c0w + nt*8 + (l & 3)*2;
            float b0 = 0.f, b1 = 0.f;
            if (bias) { b0 = bias[col]; b1 = bias[col + 1]; }
            #pragma unroll
            for (int hf = 0; hf < 2; hf++) {
                int row = r0w + mt*16 + (l >> 2) + hf*8;
                float v0 = acc[mt][nt][hf*2 + 0] + b0;
                float v1 = acc[mt][nt][hf*2 + 1] + b1;
                float2 o; o.x = v0; o.y = v1;
                *(float2*)&C[(size_t)row*ldc + col] = o;
                if (Chi) {
                    __nv_bfloat162 h2, l2;
                    h2.x = __float2bfloat16(v0);
                    l2.x = __float2bfloat16(v0 - __bfloat162float(h2.x));
                    h2.y = __float2bfloat16(v1);
                    l2.y = __float2bfloat16(v1 - __bfloat162float(h2.y));
                    *(__nv_bfloat162*)&Chi[(size_t)row*ldc + col] = h2;
                    *(__nv_bfloat162*)&Clo[(size_t)row*ldc + col] = l2;
                }
            }
        }
    }
}

// ================= s_l, s_r =================
__global__ void s_kernel(const float* __restrict__ gat_a, int l) {
    int t = blockIdx.x * 256 + threadIdx.x;   // t < MR*NHEAD
    int row = t >> 2;
    int h = t & 3;
    int b = row / ND, n = row - b*ND;
    const float* hw = &g_hW[row*NHID + h*NOUT];
    const float* al = &gat_a[(l*NHEAD + h)*2*NOUT];
    float sl = 0.f, sr = 0.f;
    #pragma unroll 8
    for (int e = 0; e < NOUT; e++) {
        float v = hw[e];
        sl += v * al[e];
        sr += v * al[NOUT + e];
    }
    int bh = b*NHEAD + h;
    g_sl[bh*ND + n] = sl;
    g_sr[bh*ND + n] = sr;
}

// ================= scans / sort / attention =================
__device__ __forceinline__ float warp_incl_scan(float v) {
    int lane = threadIdx.x & 31;
    #pragma unroll
    for (int o = 1; o < 32; o <<= 1) {
        float t = __shfl_up_sync(0xffffffffu, v, o);
        if (lane >= o) v += t;
    }
    return v;
}
__device__ float block_incl_scan_1024(float v, float* ws) {
    __syncthreads();
    int lane = threadIdx.x & 31, w = threadIdx.x >> 5;
    v = warp_incl_scan(v);
    if (lane == 31) ws[w] = v;
    __syncthreads();
    if (w == 0) {
        float x = ws[lane];
        x = warp_incl_scan(x);
        ws[lane] = x;
    }
    __syncthreads();
    if (w > 0) v += ws[w - 1];
    return v;
}

__global__ __launch_bounds__(1024) void prep_sort_kernel() {
    __shared__ float key[1024];
    __shared__ int   sidx[1024];
    __shared__ float ws[32];
    int bh = blockIdx.x, tid = threadIdx.x;
    key[tid] = g_sr[bh*ND + tid];
    sidx[tid] = tid;
    __syncthreads();
    for (int k = 2; k <= 1024; k <<= 1) {
        for (int j = k >> 1; j > 0; j >>= 1) {
            int ixj = tid ^ j;
            if (ixj > tid) {
                float a = key[tid], c = key[ixj];
                bool asc = (tid & k) == 0;
                if (asc ? (a > c) : (a < c)) {
                    key[tid] = c; key[ixj] = a;
                    int t = sidx[tid]; sidx[tid] = sidx[ixj]; sidx[ixj] = t;
                }
            }
            __syncthreads();
        }
    }
    float kv = key[tid];
    float whi = __expf(kv);
    float wlo = __expf(ALPHA_F * kv);
    int gb = bh*ND + tid;
    g_skey[gb] = kv;
    g_sidx[gb] = sidx[tid];
    g_whi[gb] = whi;
    g_wlo[gb] = wlo;

    float Ilo = block_incl_scan_1024(wlo, ws);
    g_zlo[bh*(ND+1) + tid + 1] = Ilo;

    float kr = key[1023 - tid];
    float whr = __expf(kr);
    float Ir = block_incl_scan_1024(whr, ws);
    g_zhi[bh*(ND+1) + (1023 - tid)] = Ir;
    if (tid == 0) {
        g_zlo[bh*(ND+1)] = 0.f;
        g_zhi[bh*(ND+1) + ND] = 0.f;
    }
}

__global__ __launch_bounds__(1024) void prep_scan_kernel() {
    __shared__ float ws[32];
    __shared__ float tot_s;
    int e = blockIdx.x, bh = blockIdx.y, tid = threadIdx.x;
    int b = bh >> 2, h = bh & 3;
    int m = g_sidx[bh*ND + tid];
    float hv = g_hW[(b*ND + m)*NHID + h*NOUT + e];
    float vlo = g_wlo[bh*ND + tid] * hv;
    float vhi = g_whi[bh*ND + tid] * hv;

    float Ilo = block_incl_scan_1024(vlo, ws);
    float Ihi = block_incl_scan_1024(vhi, ws);
    if (tid == 1023) tot_s = Ihi;
    __syncthreads();
    float Tot = tot_s;

    int base = bh*(ND+1)*NOUT + e;
    g_pref[base + (tid + 1)*NOUT] = Ilo;
    g_suf[base + tid*NOUT] = Tot - (Ihi - vhi);
    if (tid == 0) {
        g_pref[base] = 0.f;
        g_suf[base + ND*NOUT] = 0.f;
    }
}

__global__ __launch_bounds__(256) void attn_apply_kernel() {
    __shared__ float skey_s[1024];
    int bh = blockIdx.y;
    int b = bh >> 2, h = bh & 3;
    int tid = threadIdx.x;
    int warp = tid >> 5, lane = tid & 31;
    for (int i = tid; i < 1024; i += 256) skey_s[i] = g_skey[bh*ND + i];
    __syncthreads();
    int nbase = blockIdx.x * 128 + warp * 16;
    for (int it = 0; it < 16; it++) {
        int n = nbase + it;
        float sl = g_sl[bh*ND + n];
        float thr = -sl;
        int lo = 0, hi = 1024;
        while (lo < hi) {
            int mid = (lo + hi) >> 1;
            if (skey_s[mid] > thr) hi = mid; else lo = mid + 1;
        }
        int k = lo;
        float esl = __expf(sl);
        float eal = __expf(ALPHA_F * sl);
        float Z = esl * g_zhi[bh*(ND+1) + k] + eal * g_zlo[bh*(ND+1) + k];
        float invZ = 1.0f / Z;
        const float* suf = &g_suf[(bh*(ND+1) + k)*NOUT];
        const float* pre = &g_pref[(bh*(ND+1) + k)*NOUT];
        float v0 = (esl * suf[lane]      + eal * pre[lane])      * invZ;
        float v1 = (esl * suf[lane + 32] + eal * pre[lane + 32]) * invZ;
        int orow = (b*ND + n)*NHID + h*NOUT;
        g_hout[orow + lane] = v0;
        g_hout[orow + lane + 32] = v1;
    }
}

// ================= residual + layernorm + bf16 split =================
__device__ float block_sum_256(float v, float* ws) {
    __syncthreads();
    int lane = threadIdx.x & 31, w = threadIdx.x >> 5;
    #pragma unroll
    for (int o = 16; o > 0; o >>= 1) v += __shfl_xor_sync(0xffffffffu, v, o);
    if (lane == 0) ws[w] = v;
    __syncthreads();
    if (threadIdx.x == 0) {
        float s = 0.f;
        #pragma unroll
        for (int i = 0; i < 8; i++) s += ws[i];
        ws[8] = s;
    }
    __syncthreads();
    return ws[8];
}

__global__ __launch_bounds__(256) void ln_kernel(const float* __restrict__ ln_g,
                                                 const float* __restrict__ ln_b, int l) {
    __shared__ float ws[9];
    int row = blockIdx.x, tid = threadIdx.x;
    float v = g_h[row*NHID + tid] + g_hout[row*NHID + tid];
    float mu = block_sum_256(v, ws) * (1.0f / NHID);
    float d = v - mu;
    float var = block_sum_256(d*d, ws) * (1.0f / NHID);
    float o = d * rsqrtf(var + EPS_F) * ln_g[l*NHID + tid] + ln_b[l*NHID + tid];
    g_h[row*NHID + tid] = o;
    __nv_bfloat16 hi = __float2bfloat16(o);
    g_hh[row*NHID + tid] = hi;
    g_hl[row*NHID + tid] = __float2bfloat16(o - __bfloat162float(hi));
}

// ================= launch =================
extern "C" void kernel_launch(void* const* d_in, const int* in_sizes, int n_in,
                              void* d_out, int out_size) {
    const float* X     = (const float*)d_in[0];
    const float* Mk    = (const float*)d_in[1];
    const float* W_in  = (const float*)d_in[2];
    const float* b_in  = (const float*)d_in[3];
    const float* gat_W = (const float*)d_in[4];
    const float* gat_a = (const float*)d_in[5];
    const float* ln_g  = (const float*)d_in[6];
    const float* ln_b  = (const float*)d_in[7];
    const float* W_out = (const float*)d_in[8];
    const float* b_out = (const float*)d_in[9];
    float* out = (float*)d_out;

    __nv_bfloat16 *p_Axh, *p_Axl, *p_WinTh, *p_WinTl, *p_WcatTh, *p_WcatTl, *p_WoutTh, *p_WoutTl, *p_hh, *p_hl;
    float *p_h, *p_hW;
    cudaGetSymbolAddress((void**)&p_Axh, g_Axh);
    cudaGetSymbolAddress((void**)&p_Axl, g_Axl);
    cudaGetSymbolAddress((void**)&p_WinTh, g_WinTh);
    cudaGetSymbolAddress((void**)&p_WinTl, g_WinTl);
    cudaGetSymbolAddress((void**)&p_WcatTh, g_WcatTh);
    cudaGetSymbolAddress((void**)&p_WcatTl, g_WcatTl);
    cudaGetSymbolAddress((void**)&p_WoutTh, g_WoutTh);
    cudaGetSymbolAddress((void**)&p_WoutTl, g_WoutTl);
    cudaGetSymbolAddress((void**)&p_hh, g_hh);
    cudaGetSymbolAddress((void**)&p_hl, g_hl);
    cudaGetSymbolAddress((void**)&p_h, g_h);
    cudaGetSymbolAddress((void**)&p_hW, g_hW);

    posmean_kernel<<<(ND*NT)/256, 256>>>(X, Mk);
    xcat_bf16_kernel<<<(NB*ND*NT)/256, 256>>>(X, Mk);

    // W_in [1024][256] -> WinT [256][1024] (hi/lo)
    transconv_kernel<<<dim3(NHID/32, (2*NT)/32, 1), dim3(32,8)>>>(
        W_in, 2*NT, NHID, p_WinTh, p_WinTl, 2*NT, 0, 0);

    // h = xcat @ W_in + b_in  (M=8192, N=256, K=1024), split output for next GEMM
    mma_gemm_kernel<<<dim3(NHID/128, MR/128), 256>>>(
        2*NT, 2*NT, 2*NT, NHID, p_Axh, p_Axl, p_WinTh, p_WinTl, b_in, p_h, p_hh, p_hl);

    for (int l = 0; l < NLAY; l++) {
        // gat_W[l] (h,k,e) -> WcatT[n=h*64+e][k] (hi/lo)
        transconv_kernel<<<dim3(NOUT/32, NHID/32, NHEAD), dim3(32,8)>>>(
            gat_W + (size_t)l*NHEAD*NHID*NOUT, NHID, NOUT,
            p_WcatTh, p_WcatTl, NHID, NOUT, NHID*NOUT);
        // hW = h @ Wcat  (M=8192, N=256, K=256)
        mma_gemm_kernel<<<dim3(NHID/128, MR/128), 256>>>(
            NHID, NHID, NHID, NHID, p_hh, p_hl, p_WcatTh, p_WcatTl, nullptr, p_hW, nullptr, nullptr);
        s_kernel<<<(MR*NHEAD)/256, 256>>>(gat_a, l);
        prep_sort_kernel<<<NBH, 1024>>>();
        prep_scan_kernel<<<dim3(NOUT, NBH), 1024>>>();
        attn_apply_kernel<<<dim3(ND/128, NBH), 256>>>();
        ln_kernel<<<MR, 256>>>(ln_g, ln_b, l);
    }

    // W_out [256][512] -> WoutT [512][256] (hi/lo)
    transconv_kernel<<<dim3(NT/32, NHID/32, 1), dim3(32,8)>>>(
        W_out, NHID, NT, p_WoutTh, p_WoutTl, NHID, 0, 0);
    // out = h @ W_out + b_out  (M=8192, N=512, K=256)
    mma_gemm_kernel<<<dim3(NT/128, MR/128), 256>>>(
        NHID, NHID, NHID, NT, p_hh, p_hl, p_WoutTh, p_WoutTl, b_out, out, nullptr, nullptr);
}

// round 16
// speedup vs baseline: 1.4612x; 1.0670x over previous
#include <cuda_runtime.h>
#include <cuda_bf16.h>
#include <cstdint>

#define NB 8
#define ND 1024
#define NT 512
#define NHID 256
#define NHEAD 4
#define NLAY 2
#define NOUT 64
#define MR (NB*ND)          // 8192 rows
#define NBH (NB*NHEAD)      // 32 batch-heads
#define ALPHA_F 0.2f
#define EPS_F 1e-5f

#define SMEM_SWIZZLE_128B(b) ((b) ^ (((b) >> 3) & 0x70))

#define GSTAGES 4
#define STAGE_BYTES 32768
#define GSMEM_BYTES (GSTAGES*STAGE_BYTES + 1024)

__device__ __forceinline__ uint32_t smem_to_u32(const void* p) {
    uint32_t a;
    asm("{ .reg .u64 t; cvta.to.shared.u64 t, %1; cvt.u32.u64 %0, t; }" : "=r"(a) : "l"(p));
    return a;
}
__device__ __forceinline__ void ldsm_x4(uint32_t* r, uint32_t addr) {
    asm volatile("ldmatrix.sync.aligned.m8n8.x4.shared.b16 {%0,%1,%2,%3}, [%4];"
        : "=r"(r[0]), "=r"(r[1]), "=r"(r[2]), "=r"(r[3]) : "r"(addr));
}
__device__ __forceinline__ void ldsm_x2(uint32_t* r, uint32_t addr) {
    asm volatile("ldmatrix.sync.aligned.m8n8.x2.shared.b16 {%0,%1}, [%2];"
        : "=r"(r[0]), "=r"(r[1]) : "r"(addr));
}
__device__ __forceinline__ void mma16816(float* c, const uint32_t* a, const uint32_t* b) {
    asm volatile("mma.sync.aligned.m16n8k16.row.col.f32.bf16.bf16.f32 "
        "{%0,%1,%2,%3}, {%4,%5,%6,%7}, {%8,%9}, {%0,%1,%2,%3};"
        : "+f"(c[0]), "+f"(c[1]), "+f"(c[2]), "+f"(c[3])
        : "r"(a[0]), "r"(a[1]), "r"(a[2]), "r"(a[3]), "r"(b[0]), "r"(b[1]));
}
__device__ __forceinline__ void cp_async16(uint32_t saddr, const void* gaddr) {
    asm volatile("cp.async.cg.shared.global [%0], [%1], 16;" :: "r"(saddr), "l"(gaddr));
}

// ================= scratch =================
__device__ float g_posmean[ND*NT];
__device__ __nv_bfloat16 g_Axh[MR*(2*NT)];
__device__ __nv_bfloat16 g_Axl[MR*(2*NT)];
__device__ __nv_bfloat16 g_WinTh[NHID*(2*NT)];
__device__ __nv_bfloat16 g_WinTl[NHID*(2*NT)];
__device__ __nv_bfloat16 g_WcatTh[NHID*NHID];
__device__ __nv_bfloat16 g_WcatTl[NHID*NHID];
__device__ __nv_bfloat16 g_WoutTh[NT*NHID];
__device__ __nv_bfloat16 g_WoutTl[NT*NHID];
__device__ float g_h[MR*NHID];
__device__ __nv_bfloat16 g_hh[MR*NHID];
__device__ __nv_bfloat16 g_hl[MR*NHID];
__device__ float g_hW[MR*NHID];
__device__ float g_sl[NBH*ND];
__device__ float g_sr[NBH*ND];
__device__ float g_skey[NBH*ND];
__device__ int   g_sidx[NBH*ND];
__device__ float g_whi[NBH*ND];
__device__ float g_wlo[NBH*ND];
__device__ float g_zhi[NBH*(ND+1)];
__device__ float g_zlo[NBH*(ND+1)];
__device__ float g_suf[NBH*(ND+1)*NOUT];
__device__ float g_pref[NBH*(ND+1)*NOUT];
__device__ float g_hout[MR*NHID];

// ================= elementwise front =================
__global__ void posmean_kernel(const float* __restrict__ X, const float* __restrict__ Mk) {
    int i = blockIdx.x * 256 + threadIdx.x;
    float s = 0.f, c = 0.f;
    #pragma unroll
    for (int b = 0; b < NB; b++) {
        float m = Mk[b*ND*NT + i];
        s += X[b*ND*NT + i] * m;
        c += m;
    }
    g_posmean[i] = s / (c + 1e-10f);
}

__global__ void xcat_bf16_kernel(const float* __restrict__ X, const float* __restrict__ Mk) {
    int i = blockIdx.x * 256 + threadIdx.x;            // i < NB*ND*NT
    int r = i / NT;
    int t = i - r * NT;
    int p = i % (ND*NT);
    float m = Mk[i];
    float x = X[i];
    float pm = g_posmean[p];
    float xm = x*m + (1.f - m)*pm;
    __nv_bfloat16 hi = __float2bfloat16(xm);
    __nv_bfloat16 lo = __float2bfloat16(xm - __bfloat162float(hi));
    size_t base = (size_t)r * (2*NT);
    g_Axh[base + t] = hi;
    g_Axl[base + t] = lo;
    g_Axh[base + NT + t] = __float2bfloat16(m);   // 0/1 exact
    g_Axl[base + NT + t] = __float2bfloat16(0.f);
}

// ================= transpose + fp32->bf16 hi/lo split =================
__global__ void transconv_kernel(const float* __restrict__ src, int R, int C,
                                 __nv_bfloat16* __restrict__ dhi, __nv_bfloat16* __restrict__ dlo,
                                 int dld, int drows_per_batch, int sbatch) {
    __shared__ float t[32][33];
    const float* s = src + (size_t)blockIdx.z * sbatch;
    int r0 = blockIdx.y * 32, c0 = blockIdx.x * 32;
    int tx = threadIdx.x, ty = threadIdx.y;
    #pragma unroll
    for (int i = 0; i < 4; i++)
        t[ty + 8*i][tx] = s[(size_t)(r0 + ty + 8*i)*C + c0 + tx];
    __syncthreads();
    int drow0 = blockIdx.z * drows_per_batch;
    #pragma unroll
    for (int i = 0; i < 4; i++) {
        int c = ty + 8*i;
        float v = t[tx][c];
        __nv_bfloat16 hi = __float2bfloat16(v);
        __nv_bfloat16 lo = __float2bfloat16(v - __bfloat162float(hi));
        size_t o = (size_t)(drow0 + c0 + c)*dld + r0 + tx;
        dhi[o] = hi; dlo[o] = lo;
    }
}

// ================= bf16x3 HMMA GEMM, cp.async 4-stage pipeline =================
// C[M,N] = A[M,K] @ Bt[N,K]^T via 3 passes: Ahi*Bhi + Alo*Bhi + Ahi*Blo.
// CTA 128x128, 8 warps of 64x32, BK=64, mma.sync m16n8k16.
__global__ __launch_bounds__(256) void mma_gemm_kernel(
    int K, int lda, int ldb, int ldc,
    const __nv_bfloat16* __restrict__ Ahi, const __nv_bfloat16* __restrict__ Alo,
    const __nv_bfloat16* __restrict__ Bhi, const __nv_bfloat16* __restrict__ Blo,
    const float* __restrict__ bias, float* __restrict__ C,
    __nv_bfloat16* __restrict__ Chi, __nv_bfloat16* __restrict__ Clo)
{
    extern __shared__ char smem_raw[];
    uint32_t sBase = (smem_to_u32(smem_raw) + 1023) & ~1023u;
    const int tid = threadIdx.x;
    const int w = tid >> 5, l = tid & 31;
    const int m0 = blockIdx.y * 128, n0 = blockIdx.x * 128;
    const int wm = w >> 2, wn = w & 3;       // warp tile: rows wm*64, cols wn*32

    float acc[4][4][4];
    #pragma unroll
    for (int i = 0; i < 4; i++)
        #pragma unroll
        for (int j = 0; j < 4; j++)
            #pragma unroll
            for (int q = 0; q < 4; q++) acc[i][j][q] = 0.f;

    const int rbase = w*16 + (l >> 3);       // each thread: 4 rows, one 16B column chunk
    const int c16 = l & 7;
    const int kchunks = K >> 6;
    const int nch = 3 * kchunks;

    auto issue_chunk = [&](int c) {
        if (c < nch) {
            int stage = c & (GSTAGES - 1);
            int p = c / kchunks;
            int k0 = (c - p * kchunks) << 6;
            const __nv_bfloat16* As = (p == 1) ? Alo : Ahi;
            const __nv_bfloat16* Bs = (p == 2) ? Blo : Bhi;
            uint32_t dA = sBase + stage * STAGE_BYTES;
            uint32_t dB = dA + 16384;
            #pragma unroll
            for (int i = 0; i < 4; i++) {
                int row = rbase + i*4;
                uint32_t sw = SMEM_SWIZZLE_128B(row*128 + c16*16);
                cp_async16(dA + sw, As + (size_t)(m0 + row)*lda + k0 + c16*8);
                cp_async16(dB + sw, Bs + (size_t)(n0 + row)*ldb + k0 + c16*8);
            }
        }
        asm volatile("cp.async.commit_group;" ::: "memory");
    };

    issue_chunk(0);
    issue_chunk(1);
    issue_chunk(2);

    const int arow = wm*64 + (l & 15);
    const int akh = l >> 4;
    const int brow = wn*32 + (l & 7);
    const int bkh = (l >> 3) & 1;

    for (int c = 0; c < nch; c++) {
        asm volatile("cp.async.wait_group %0;" :: "n"(GSTAGES - 2) : "memory");  // chunk c arrived
        __syncthreads();                    // all warps done computing chunk c-1
        issue_chunk(c + GSTAGES - 1);       // refill the stage freed last iteration

        uint32_t aT = sBase + (c & (GSTAGES - 1)) * STAGE_BYTES;
        uint32_t bT = aT + 16384;
        #pragma unroll
        for (int kk = 0; kk < 4; kk++) {
            uint32_t af[4][4], bf_[4][2];
            #pragma unroll
            for (int mt = 0; mt < 4; mt++)
                ldsm_x4(af[mt], aT + SMEM_SWIZZLE_128B((arow + mt*16)*128 + kk*32 + akh*16));
            #pragma unroll
            for (int nt = 0; nt < 4; nt++)
                ldsm_x2(bf_[nt], bT + SMEM_SWIZZLE_128B((brow + nt*8)*128 + kk*32 + bkh*16));
            #pragma unroll
            for (int mt = 0; mt < 4; mt++)
                #pragma unroll
                for (int nt = 0; nt < 4; nt++)
                    mma16816(acc[mt][nt], af[mt], bf_[nt]);
        }
    }

    // epilogue
    const int r0w = m0 + wm*64;
    const int c0w = n0 + wn*32;
    #pragma unroll
    for (int mt = 0; mt < 4; mt++) {
        #pragma unroll
        for (int nt = 0; nt < 4; nt++) {
            int col = c0w + nt*8 + (l & 3)*2;
            float b0 = 0.f, b1 = 0.f;
            if (bias) { b0 = bias[col]; b1 = bias[col + 1]; }
            #pragma unroll
            for (int hf = 0; hf < 2; hf++) {
                int row = r0w + mt*16 + (l >> 2) + hf*8;
                float v0 = acc[mt][nt][hf*2 + 0] + b0;
                float v1 = acc[mt][nt][hf*2 + 1] + b1;
                float2 o; o.x = v0; o.y = v1;
                *(float2*)&C[(size_t)row*ldc + col] = o;
                if (Chi) {
                    __nv_bfloat162 h2, l2;
                    h2.x = __float2bfloat16(v0);
                    l2.x = __float2bfloat16(v0 - __bfloat162float(h2.x));
                    h2.y = __float2bfloat16(v1);
                    l2.y = __float2bfloat16(v1 - __bfloat162float(h2.y));
                    *(__nv_bfloat162*)&Chi[(size_t)row*ldc + col] = h2;
                    *(__nv_bfloat162*)&Clo[(size_t)row*ldc + col] = l2;
                }
            }
        }
    }
}

// ================= s_l, s_r =================
__global__ void s_kernel(const float* __restrict__ gat_a, int l) {
    int t = blockIdx.x * 256 + threadIdx.x;   // t < MR*NHEAD
    int row = t >> 2;
    int h = t & 3;
    int b = row / ND, n = row - b*ND;
    const float* hw = &g_hW[row*NHID + h*NOUT];
    const float* al = &gat_a[(l*NHEAD + h)*2*NOUT];
    float sl = 0.f, sr = 0.f;
    #pragma unroll 8
    for (int e = 0; e < NOUT; e++) {
        float v = hw[e];
        sl += v * al[e];
        sr += v * al[NOUT + e];
    }
    int bh = b*NHEAD + h;
    g_sl[bh*ND + n] = sl;
    g_sr[bh*ND + n] = sr;
}

// ================= scans / sort / attention =================
__device__ __forceinline__ float warp_incl_scan(float v) {
    int lane = threadIdx.x & 31;
    #pragma unroll
    for (int o = 1; o < 32; o <<= 1) {
        float t = __shfl_up_sync(0xffffffffu, v, o);
        if (lane >= o) v += t;
    }
    return v;
}
__device__ float block_incl_scan_1024(float v, float* ws) {
    __syncthreads();
    int lane = threadIdx.x & 31, w = threadIdx.x >> 5;
    v = warp_incl_scan(v);
    if (lane == 31) ws[w] = v;
    __syncthreads();
    if (w == 0) {
        float x = ws[lane];
        x = warp_incl_scan(x);
        ws[lane] = x;
    }
    __syncthreads();
    if (w > 0) v += ws[w - 1];
    return v;
}

__global__ __launch_bounds__(1024) void prep_sort_kernel() {
    __shared__ float key[1024];
    __shared__ int   sidx[1024];
    __shared__ float ws[32];
    int bh = blockIdx.x, tid = threadIdx.x;
    key[tid] = g_sr[bh*ND + tid];
    sidx[tid] = tid;
    __syncthreads();
    for (int k = 2; k <= 1024; k <<= 1) {
        for (int j = k >> 1; j > 0; j >>= 1) {
            int ixj = tid ^ j;
            if (ixj > tid) {
                float a = key[tid], c = key[ixj];
                bool asc = (tid & k) == 0;
                if (asc ? (a > c) : (a < c)) {
                    key[tid] = c; key[ixj] = a;
                    int t = sidx[tid]; sidx[tid] = sidx[ixj]; sidx[ixj] = t;
                }
            }
            __syncthreads();
        }
    }
    float kv = key[tid];
    float whi = __expf(kv);
    float wlo = __expf(ALPHA_F * kv);
    int gb = bh*ND + tid;
    g_skey[gb] = kv;
    g_sidx[gb] = sidx[tid];
    g_whi[gb] = whi;
    g_wlo[gb] = wlo;

    float Ilo = block_incl_scan_1024(wlo, ws);
    g_zlo[bh*(ND+1) + tid + 1] = Ilo;

    float kr = key[1023 - tid];
    float whr = __expf(kr);
    float Ir = block_incl_scan_1024(whr, ws);
    g_zhi[bh*(ND+1) + (1023 - tid)] = Ir;
    if (tid == 0) {
        g_zlo[bh*(ND+1)] = 0.f;
        g_zhi[bh*(ND+1) + ND] = 0.f;
    }
}

__global__ __launch_bounds__(1024) void prep_scan_kernel() {
    __shared__ float ws[32];
    __shared__ float tot_s;
    int e = blockIdx.x, bh = blockIdx.y, tid = threadIdx.x;
    int b = bh >> 2, h = bh & 3;
    int m = g_sidx[bh*ND + tid];
    float hv = g_hW[(b*ND + m)*NHID + h*NOUT + e];
    float vlo = g_wlo[bh*ND + tid] * hv;
    float vhi = g_whi[bh*ND + tid] * hv;

    float Ilo = block_incl_scan_1024(vlo, ws);
    float Ihi = block_incl_scan_1024(vhi, ws);
    if (tid == 1023) tot_s = Ihi;
    __syncthreads();
    float Tot = tot_s;

    int base = bh*(ND+1)*NOUT + e;
    g_pref[base + (tid + 1)*NOUT] = Ilo;
    g_suf[base + tid*NOUT] = Tot - (Ihi - vhi);
    if (tid == 0) {
        g_pref[base] = 0.f;
        g_suf[base + ND*NOUT] = 0.f;
    }
}

__global__ __launch_bounds__(256) void attn_apply_kernel() {
    __shared__ float skey_s[1024];
    int bh = blockIdx.y;
    int b = bh >> 2, h = bh & 3;
    int tid = threadIdx.x;
    int warp = tid >> 5, lane = tid & 31;
    for (int i = tid; i < 1024; i += 256) skey_s[i] = g_skey[bh*ND + i];
    __syncthreads();
    int nbase = blockIdx.x * 128 + warp * 16;
    for (int it = 0; it < 16; it++) {
        int n = nbase + it;
        float sl = g_sl[bh*ND + n];
        float thr = -sl;
        int lo = 0, hi = 1024;
        while (lo < hi) {
            int mid = (lo + hi) >> 1;
            if (skey_s[mid] > thr) hi = mid; else lo = mid + 1;
        }
        int k = lo;
        float esl = __expf(sl);
        float eal = __expf(ALPHA_F * sl);
        float Z = esl * g_zhi[bh*(ND+1) + k] + eal * g_zlo[bh*(ND+1) + k];
        float invZ = 1.0f / Z;
        const float* suf = &g_suf[(bh*(ND+1) + k)*NOUT];
        const float* pre = &g_pref[(bh*(ND+1) + k)*NOUT];
        float v0 = (esl * suf[lane]      + eal * pre[lane])      * invZ;
        float v1 = (esl * suf[lane + 32] + eal * pre[lane + 32]) * invZ;
        int orow = (b*ND + n)*NHID + h*NOUT;
        g_hout[orow + lane] = v0;
        g_hout[orow + lane + 32] = v1;
    }
}

// ================= residual + layernorm + bf16 split =================
__device__ float block_sum_256(float v, float* ws) {
    __syncthreads();
    int lane = threadIdx.x & 31, w = threadIdx.x >> 5;
    #pragma unroll
    for (int o = 16; o > 0; o >>= 1) v += __shfl_xor_sync(0xffffffffu, v, o);
    if (lane == 0) ws[w] = v;
    __syncthreads();
    if (threadIdx.x == 0) {
        float s = 0.f;
        #pragma unroll
        for (int i = 0; i < 8; i++) s += ws[i];
        ws[8] = s;
    }
    __syncthreads();
    return ws[8];
}

__global__ __launch_bounds__(256) void ln_kernel(const float* __restrict__ ln_g,
                                                 const float* __restrict__ ln_b, int l) {
    __shared__ float ws[9];
    int row = blockIdx.x, tid = threadIdx.x;
    float v = g_h[row*NHID + tid] + g_hout[row*NHID + tid];
    float mu = block_sum_256(v, ws) * (1.0f / NHID);
    float d = v - mu;
    float var = block_sum_256(d*d, ws) * (1.0f / NHID);
    float o = d * rsqrtf(var + EPS_F) * ln_g[l*NHID + tid] + ln_b[l*NHID + tid];
    g_h[row*NHID + tid] = o;
    __nv_bfloat16 hi = __float2bfloat16(o);
    g_hh[row*NHID + tid] = hi;
    g_hl[row*NHID + tid] = __float2bfloat16(o - __bfloat162float(hi));
}

// ================= launch =================
extern "C" void kernel_launch(void* const* d_in, const int* in_sizes, int n_in,
                              void* d_out, int out_size) {
    const float* X     = (const float*)d_in[0];
    const float* Mk    = (const float*)d_in[1];
    const float* W_in  = (const float*)d_in[2];
    const float* b_in  = (const float*)d_in[3];
    const float* gat_W = (const float*)d_in[4];
    const float* gat_a = (const float*)d_in[5];
    const float* ln_g  = (const float*)d_in[6];
    const float* ln_b  = (const float*)d_in[7];
    const float* W_out = (const float*)d_in[8];
    const float* b_out = (const float*)d_in[9];
    float* out = (float*)d_out;

    cudaFuncSetAttribute(mma_gemm_kernel, cudaFuncAttributeMaxDynamicSharedMemorySize, GSMEM_BYTES);

    __nv_bfloat16 *p_Axh, *p_Axl, *p_WinTh, *p_WinTl, *p_WcatTh, *p_WcatTl, *p_WoutTh, *p_WoutTl, *p_hh, *p_hl;
    float *p_h, *p_hW;
    cudaGetSymbolAddress((void**)&p_Axh, g_Axh);
    cudaGetSymbolAddress((void**)&p_Axl, g_Axl);
    cudaGetSymbolAddress((void**)&p_WinTh, g_WinTh);
    cudaGetSymbolAddress((void**)&p_WinTl, g_WinTl);
    cudaGetSymbolAddress((void**)&p_WcatTh, g_WcatTh);
    cudaGetSymbolAddress((void**)&p_WcatTl, g_WcatTl);
    cudaGetSymbolAddress((void**)&p_WoutTh, g_WoutTh);
    cudaGetSymbolAddress((void**)&p_WoutTl, g_WoutTl);
    cudaGetSymbolAddress((void**)&p_hh, g_hh);
    cudaGetSymbolAddress((void**)&p_hl, g_hl);
    cudaGetSymbolAddress((void**)&p_h, g_h);
    cudaGetSymbolAddress((void**)&p_hW, g_hW);

    posmean_kernel<<<(ND*NT)/256, 256>>>(X, Mk);
    xcat_bf16_kernel<<<(NB*ND*NT)/256, 256>>>(X, Mk);

    // W_in [1024][256] -> WinT [256][1024] (hi/lo)
    transconv_kernel<<<dim3(NHID/32, (2*NT)/32, 1), dim3(32,8)>>>(
        W_in, 2*NT, NHID, p_WinTh, p_WinTl, 2*NT, 0, 0);

    // h = xcat @ W_in + b_in  (M=8192, N=256, K=1024), split output for next GEMM
    mma_gemm_kernel<<<dim3(NHID/128, MR/128), 256, GSMEM_BYTES>>>(
        2*NT, 2*NT, 2*NT, NHID, p_Axh, p_Axl, p_WinTh, p_WinTl, b_in, p_h, p_hh, p_hl);

    for (int l = 0; l < NLAY; l++) {
        // gat_W[l] (h,k,e) -> WcatT[n=h*64+e][k] (hi/lo)
        transconv_kernel<<<dim3(NOUT/32, NHID/32, NHEAD), dim3(32,8)>>>(
            gat_W + (size_t)l*NHEAD*NHID*NOUT, NHID, NOUT,
            p_WcatTh, p_WcatTl, NHID, NOUT, NHID*NOUT);
        // hW = h @ Wcat  (M=8192, N=256, K=256)
        mma_gemm_kernel<<<dim3(NHID/128, MR/128), 256, GSMEM_BYTES>>>(
            NHID, NHID, NHID, NHID, p_hh, p_hl, p_WcatTh, p_WcatTl, nullptr, p_hW, nullptr, nullptr);
        s_kernel<<<(MR*NHEAD)/256, 256>>>(gat_a, l);
        prep_sort_kernel<<<NBH, 1024>>>();
        prep_scan_kernel<<<dim3(NOUT, NBH), 1024>>>();
        attn_apply_kernel<<<dim3(ND/128, NBH), 256>>>();
        ln_kernel<<<MR, 256>>>(ln_g, ln_b, l);
    }

    // W_out [256][512] -> WoutT [512][256] (hi/lo)
    transconv_kernel<<<dim3(NT/32, NHID/32, 1), dim3(32,8)>>>(
        W_out, NHID, NT, p_WoutTh, p_WoutTl, NHID, 0, 0);
    // out = h @ W_out + b_out  (M=8192, N=512, K=256)
    mma_gemm_kernel<<<dim3(NT/128, MR/128), 256, GSMEM_BYTES>>>(
        NHID, NHID, NHID, NT, p_hh, p_hl, p_WoutTh, p_WoutTl, b_out, out, nullptr, nullptr);
}

// round 17
// speedup vs baseline: 1.7140x; 1.1731x over previous
#include <cuda_runtime.h>
#include <cuda_bf16.h>
#include <cstdint>

#define NB 8
#define ND 1024
#define NT 512
#define NHID 256
#define NHEAD 4
#define NLAY 2
#define NOUT 64
#define MR (NB*ND)          // 8192 rows
#define NBH (NB*NHEAD)      // 32 batch-heads
#define ALPHA_F 0.2f
#define EPS_F 1e-5f
#define NSEG 4
#define SEGK (ND/NSEG)      // 256

#define SMEM_SWIZZLE_128B(b) ((b) ^ (((b) >> 3) & 0x70))

#define GSTAGES 4
#define STAGE_BYTES 32768
#define GSMEM_BYTES (GSTAGES*STAGE_BYTES + 1024)

__device__ __forceinline__ uint32_t smem_to_u32(const void* p) {
    uint32_t a;
    asm("{ .reg .u64 t; cvta.to.shared.u64 t, %1; cvt.u32.u64 %0, t; }" : "=r"(a) : "l"(p));
    return a;
}
__device__ __forceinline__ void ldsm_x4(uint32_t* r, uint32_t addr) {
    asm volatile("ldmatrix.sync.aligned.m8n8.x4.shared.b16 {%0,%1,%2,%3}, [%4];"
        : "=r"(r[0]), "=r"(r[1]), "=r"(r[2]), "=r"(r[3]) : "r"(addr));
}
__device__ __forceinline__ void ldsm_x2(uint32_t* r, uint32_t addr) {
    asm volatile("ldmatrix.sync.aligned.m8n8.x2.shared.b16 {%0,%1}, [%2];"
        : "=r"(r[0]), "=r"(r[1]) : "r"(addr));
}
__device__ __forceinline__ void mma16816(float* c, const uint32_t* a, const uint32_t* b) {
    asm volatile("mma.sync.aligned.m16n8k16.row.col.f32.bf16.bf16.f32 "
        "{%0,%1,%2,%3}, {%4,%5,%6,%7}, {%8,%9}, {%0,%1,%2,%3};"
        : "+f"(c[0]), "+f"(c[1]), "+f"(c[2]), "+f"(c[3])
        : "r"(a[0]), "r"(a[1]), "r"(a[2]), "r"(a[3]), "r"(b[0]), "r"(b[1]));
}
__device__ __forceinline__ void cp_async16(uint32_t saddr, const void* gaddr) {
    asm volatile("cp.async.cg.shared.global [%0], [%1], 16;" :: "r"(saddr), "l"(gaddr));
}

// ================= scratch =================
__device__ float g_posmean[ND*NT];
__device__ __nv_bfloat16 g_Axh[MR*(2*NT)];
__device__ __nv_bfloat16 g_Axl[MR*(2*NT)];
__device__ __nv_bfloat16 g_WinTh[NHID*(2*NT)];
__device__ __nv_bfloat16 g_WinTl[NHID*(2*NT)];
__device__ __nv_bfloat16 g_WcatTh[NHID*NHID];
__device__ __nv_bfloat16 g_WcatTl[NHID*NHID];
__device__ __nv_bfloat16 g_WoutTh[NT*NHID];
__device__ __nv_bfloat16 g_WoutTl[NT*NHID];
__device__ float g_h[MR*NHID];
__device__ __nv_bfloat16 g_hh[MR*NHID];
__device__ __nv_bfloat16 g_hl[MR*NHID];
__device__ float g_hW[MR*NHID];
__device__ float g_sl[NBH*ND];
__device__ float g_sr[NBH*ND];
__device__ float g_skey[NBH*ND];
__device__ int   g_sidx[NBH*ND];
__device__ float g_whi[NBH*ND];
__device__ float g_wlo[NBH*ND];
__device__ float g_zhi[NBH*(ND+1)];
__device__ float g_zlo[NBH*(ND+1)];
__device__ float g_PH[NBH*ND*NOUT];       // [bh][k][e] inclusive local-segment prefix of whi*hv
__device__ float g_PL[NBH*ND*NOUT];       // [bh][k][e] inclusive local-segment prefix of wlo*hv
__device__ float g_segH[NBH*NSEG*NOUT];   // per-segment totals
__device__ float g_segL[NBH*NSEG*NOUT];
__device__ float g_carrH[NBH*NSEG*NOUT];  // exclusive carry per segment
__device__ float g_carrL[NBH*NSEG*NOUT];
__device__ float g_totH[NBH*NOUT];        // full totals of whi*hv
__device__ float g_hout[MR*NHID];

// ================= elementwise front =================
__global__ void posmean_kernel(const float* __restrict__ X, const float* __restrict__ Mk) {
    int i = blockIdx.x * 256 + threadIdx.x;
    float s = 0.f, c = 0.f;
    #pragma unroll
    for (int b = 0; b < NB; b++) {
        float m = Mk[b*ND*NT + i];
        s += X[b*ND*NT + i] * m;
        c += m;
    }
    g_posmean[i] = s / (c + 1e-10f);
}

__global__ void xcat_bf16_kernel(const float* __restrict__ X, const float* __restrict__ Mk) {
    int i = blockIdx.x * 256 + threadIdx.x;            // i < NB*ND*NT
    int r = i / NT;
    int t = i - r * NT;
    int p = i % (ND*NT);
    float m = Mk[i];
    float x = X[i];
    float pm = g_posmean[p];
    float xm = x*m + (1.f - m)*pm;
    __nv_bfloat16 hi = __float2bfloat16(xm);
    __nv_bfloat16 lo = __float2bfloat16(xm - __bfloat162float(hi));
    size_t base = (size_t)r * (2*NT);
    g_Axh[base + t] = hi;
    g_Axl[base + t] = lo;
    g_Axh[base + NT + t] = __float2bfloat16(m);   // 0/1 exact
    g_Axl[base + NT + t] = __float2bfloat16(0.f); // exact zero -> pass 1 can skip K>=512
}

// ================= transpose + fp32->bf16 hi/lo split =================
__global__ void transconv_kernel(const float* __restrict__ src, int R, int C,
                                 __nv_bfloat16* __restrict__ dhi, __nv_bfloat16* __restrict__ dlo,
                                 int dld, int drows_per_batch, int sbatch) {
    __shared__ float t[32][33];
    const float* s = src + (size_t)blockIdx.z * sbatch;
    int r0 = blockIdx.y * 32, c0 = blockIdx.x * 32;
    int tx = threadIdx.x, ty = threadIdx.y;
    #pragma unroll
    for (int i = 0; i < 4; i++)
        t[ty + 8*i][tx] = s[(size_t)(r0 + ty + 8*i)*C + c0 + tx];
    __syncthreads();
    int drow0 = blockIdx.z * drows_per_batch;
    #pragma unroll
    for (int i = 0; i < 4; i++) {
        int c = ty + 8*i;
        float v = t[tx][c];
        __nv_bfloat16 hi = __float2bfloat16(v);
        __nv_bfloat16 lo = __float2bfloat16(v - __bfloat162float(hi));
        size_t o = (size_t)(drow0 + c0 + c)*dld + r0 + tx;
        dhi[o] = hi; dlo[o] = lo;
    }
}

// ================= bf16x3 HMMA GEMM, cp.async 4-stage pipeline =================
// C[M,N] = A[M,K] @ Bt[N,K]^T via 3 passes: Ahi*Bhi + Alo*Bhi + Ahi*Blo.
// Pass 1 (Alo*Bhi) may use a shorter K range K1 (Alo known zero beyond K1).
__global__ __launch_bounds__(256) void mma_gemm_kernel(
    int K, int K1, int lda, int ldb, int ldc,
    const __nv_bfloat16* __restrict__ Ahi, const __nv_bfloat16* __restrict__ Alo,
    const __nv_bfloat16* __restrict__ Bhi, const __nv_bfloat16* __restrict__ Blo,
    const float* __restrict__ bias, float* __restrict__ C,
    __nv_bfloat16* __restrict__ Chi, __nv_bfloat16* __restrict__ Clo)
{
    extern __shared__ char smem_raw[];
    uint32_t sBase = (smem_to_u32(smem_raw) + 1023) & ~1023u;
    const int tid = threadIdx.x;
    const int w = tid >> 5, l = tid & 31;
    const int m0 = blockIdx.y * 128, n0 = blockIdx.x * 128;
    const int wm = w >> 2, wn = w & 3;       // warp tile: rows wm*64, cols wn*32

    float acc[4][4][4];
    #pragma unroll
    for (int i = 0; i < 4; i++)
        #pragma unroll
        for (int j = 0; j < 4; j++)
            #pragma unroll
            for (int q = 0; q < 4; q++) acc[i][j][q] = 0.f;

    const int rbase = w*16 + (l >> 3);       // each thread: 4 rows, one 16B column chunk
    const int c16 = l & 7;
    const int kchunks = K >> 6;
    const int kch1 = K1 >> 6;
    const int nch = 2*kchunks + kch1;

    auto issue_chunk = [&](int c) {
        if (c < nch) {
            int stage = c & (GSTAGES - 1);
            int p, k0;
            if (c < kchunks)             { p = 0; k0 = c << 6; }
            else if (c < kchunks + kch1) { p = 1; k0 = (c - kchunks) << 6; }
            else                         { p = 2; k0 = (c - kchunks - kch1) << 6; }
            const __nv_bfloat16* As = (p == 1) ? Alo : Ahi;
            const __nv_bfloat16* Bs = (p == 2) ? Blo : Bhi;
            uint32_t dA = sBase + stage * STAGE_BYTES;
            uint32_t dB = dA + 16384;
            #pragma unroll
            for (int i = 0; i < 4; i++) {
                int row = rbase + i*4;
                uint32_t sw = SMEM_SWIZZLE_128B(row*128 + c16*16);
                cp_async16(dA + sw, As + (size_t)(m0 + row)*lda + k0 + c16*8);
                cp_async16(dB + sw, Bs + (size_t)(n0 + row)*ldb + k0 + c16*8);
            }
        }
        asm volatile("cp.async.commit_group;" ::: "memory");
    };

    issue_chunk(0);
    issue_chunk(1);
    issue_chunk(2);

    const int arow = wm*64 + (l & 15);
    const int akh = l >> 4;
    const int brow = wn*32 + (l & 7);
    const int bkh = (l >> 3) & 1;

    for (int c = 0; c < nch; c++) {
        asm volatile("cp.async.wait_group %0;" :: "n"(GSTAGES - 2) : "memory");  // chunk c arrived
        __syncthreads();                    // all warps done computing chunk c-1
        issue_chunk(c + GSTAGES - 1);       // refill the stage freed last iteration

        uint32_t aT = sBase + (c & (GSTAGES - 1)) * STAGE_BYTES;
        uint32_t bT = aT + 16384;
        #pragma unroll
        for (int kk = 0; kk < 4; kk++) {
            uint32_t af[4][4], bf_[4][2];
            #pragma unroll
            for (int mt = 0; mt < 4; mt++)
                ldsm_x4(af[mt], aT + SMEM_SWIZZLE_128B((arow + mt*16)*128 + kk*32 + akh*16));
            #pragma unroll
            for (int nt = 0; nt < 4; nt++)
                ldsm_x2(bf_[nt], bT + SMEM_SWIZZLE_128B((brow + nt*8)*128 + kk*32 + bkh*16));
            #pragma unroll
            for (int mt = 0; mt < 4; mt++)
                #pragma unroll
                for (int nt = 0; nt < 4; nt++)
                    mma16816(acc[mt][nt], af[mt], bf_[nt]);
        }
    }

    // epilogue
    const int r0w = m0 + wm*64;
    const int c0w = n0 + wn*32;
    #pragma unroll
    for (int mt = 0; mt < 4; mt++) {
        #pragma unroll
        for (int nt = 0; nt < 4; nt++) {
            int col = c0w + nt*8 + (l & 3)*2;
            float b0 = 0.f, b1 = 0.f;
            if (bias) { b0 = bias[col]; b1 = bias[col + 1]; }
            #pragma unroll
            for (int hf = 0; hf < 2; hf++) {
                int row = r0w + mt*16 + (l >> 2) + hf*8;
                float v0 = acc[mt][nt][hf*2 + 0] + b0;
                float v1 = acc[mt][nt][hf*2 + 1] + b1;
                float2 o; o.x = v0; o.y = v1;
                *(float2*)&C[(size_t)row*ldc + col] = o;
                if (Chi) {
                    __nv_bfloat162 h2, l2;
                    h2.x = __float2bfloat16(v0);
                    l2.x = __float2bfloat16(v0 - __bfloat162float(h2.x));
                    h2.y = __float2bfloat16(v1);
                    l2.y = __float2bfloat16(v1 - __bfloat162float(h2.y));
                    *(__nv_bfloat162*)&Chi[(size_t)row*ldc + col] = h2;
                    *(__nv_bfloat162*)&Clo[(size_t)row*ldc + col] = l2;
                }
            }
        }
    }
}

// ================= s_l, s_r =================
__global__ void s_kernel(const float* __restrict__ gat_a, int l) {
    int t = blockIdx.x * 256 + threadIdx.x;   // t < MR*NHEAD
    int row = t >> 2;
    int h = t & 3;
    int b = row / ND, n = row - b*ND;
    const float* hw = &g_hW[row*NHID + h*NOUT];
    const float* al = &gat_a[(l*NHEAD + h)*2*NOUT];
    float sl = 0.f, sr = 0.f;
    #pragma unroll 8
    for (int e = 0; e < NOUT; e++) {
        float v = hw[e];
        sl += v * al[e];
        sr += v * al[NOUT + e];
    }
    int bh = b*NHEAD + h;
    g_sl[bh*ND + n] = sl;
    g_sr[bh*ND + n] = sr;
}

// ================= scans / sort =================
__device__ __forceinline__ float warp_incl_scan(float v) {
    int lane = threadIdx.x & 31;
    #pragma unroll
    for (int o = 1; o < 32; o <<= 1) {
        float t = __shfl_up_sync(0xffffffffu, v, o);
        if (lane >= o) v += t;
    }
    return v;
}
__device__ float block_incl_scan_1024(float v, float* ws) {
    __syncthreads();
    int lane = threadIdx.x & 31, w = threadIdx.x >> 5;
    v = warp_incl_scan(v);
    if (lane == 31) ws[w] = v;
    __syncthreads();
    if (w == 0) {
        float x = ws[lane];
        x = warp_incl_scan(x);
        ws[lane] = x;
    }
    __syncthreads();
    if (w > 0) v += ws[w - 1];
    return v;
}

__global__ __launch_bounds__(1024) void prep_sort_kernel() {
    __shared__ float key[1024];
    __shared__ int   sidx[1024];
    __shared__ float ws[32];
    int bh = blockIdx.x, tid = threadIdx.x;
    key[tid] = g_sr[bh*ND + tid];
    sidx[tid] = tid;
    __syncthreads();
    for (int k = 2; k <= 1024; k <<= 1) {
        for (int j = k >> 1; j > 0; j >>= 1) {
            int ixj = tid ^ j;
            if (ixj > tid) {
                float a = key[tid], c = key[ixj];
                bool asc = (tid & k) == 0;
                if (asc ? (a > c) : (a < c)) {
                    key[tid] = c; key[ixj] = a;
                    int t = sidx[tid]; sidx[tid] = sidx[ixj]; sidx[ixj] = t;
                }
            }
            __syncthreads();
        }
    }
    float kv = key[tid];
    float whi = __expf(kv);
    float wlo = __expf(ALPHA_F * kv);
    int gb = bh*ND + tid;
    g_skey[gb] = kv;
    g_sidx[gb] = sidx[tid];
    g_whi[gb] = whi;
    g_wlo[gb] = wlo;

    float Ilo = block_incl_scan_1024(wlo, ws);
    g_zlo[bh*(ND+1) + tid + 1] = Ilo;

    float kr = key[1023 - tid];
    float whr = __expf(kr);
    float Ir = block_incl_scan_1024(whr, ws);
    g_zhi[bh*(ND+1) + (1023 - tid)] = Ir;
    if (tid == 0) {
        g_zlo[bh*(ND+1)] = 0.f;
        g_zhi[bh*(ND+1) + ND] = 0.f;
    }
}

// ================= vector prefix sums: coalesced, segmented =================
// grid (NSEG, NBH), 1024 threads = 16 k-positions x 64 e.
__global__ __launch_bounds__(1024) void prep_scan_kernel() {
    __shared__ float s_hi[16][66], s_lo[16][66];
    __shared__ float carry_hi[NOUT], carry_lo[NOUT];
    int seg = blockIdx.x, bh = blockIdx.y;
    int b = bh >> 2, h = bh & 3;
    int tid = threadIdx.x;
    if (tid < NOUT) { carry_hi[tid] = 0.f; carry_lo[tid] = 0.f; }
    const int eL = tid & 63, klL = tid >> 6;   // load/store mapping (coalesced)
    const int eS = tid >> 4, klS = tid & 15;   // scan mapping (warp-segmented)
    const int lane = tid & 31, pos = lane & 15;
    const int k0seg = seg * SEGK;
    __syncthreads();

    for (int it = 0; it < SEGK/16; it++) {
        int k = k0seg + it*16 + klL;
        int m = g_sidx[bh*ND + k];                       // broadcast across 64 threads
        float hv = g_hW[(size_t)(b*ND + m)*NHID + h*NOUT + eL];   // coalesced 256B
        float whi = g_whi[bh*ND + k];
        float wlo = g_wlo[bh*ND + k];
        s_hi[klL][eL] = whi * hv;
        s_lo[klL][eL] = wlo * hv;
        __syncthreads();

        float vh = s_hi[klS][eS], vl = s_lo[klS][eS];
        #pragma unroll
        for (int o = 1; o < 16; o <<= 1) {
            float th = __shfl_up_sync(0xffffffffu, vh, o);
            float tl = __shfl_up_sync(0xffffffffu, vl, o);
            if (pos >= o) { vh += th; vl += tl; }
        }
        float ch = carry_hi[eS], cl = carry_lo[eS];      // read by 16 lanes of one warp
        s_hi[klS][eS] = vh + ch;
        s_lo[klS][eS] = vl + cl;
        if (pos == 15) { carry_hi[eS] = ch + vh; carry_lo[eS] = cl + vl; }
        __syncthreads();

        size_t base = ((size_t)bh*ND + k)*NOUT + eL;     // coalesced store
        g_PH[base] = s_hi[klL][eL];
        g_PL[base] = s_lo[klL][eL];
        __syncthreads();
    }
    if (tid < NOUT) {
        g_segH[(bh*NSEG + seg)*NOUT + tid] = carry_hi[tid];
        g_segL[(bh*NSEG + seg)*NOUT + tid] = carry_lo[tid];
    }
}

// per (bh, e): exclusive scan of NSEG segment totals + grand total
__global__ void seg_carry_kernel() {
    int i = blockIdx.x * 256 + threadIdx.x;   // i < NBH*NOUT
    int bh = i >> 6, e = i & 63;
    float ch = 0.f, cl = 0.f;
    #pragma unroll
    for (int s = 0; s < NSEG; s++) {
        int o = (bh*NSEG + s)*NOUT + e;
        float th = g_segH[o], tl = g_segL[o];
        g_carrH[o] = ch; g_carrL[o] = cl;
        ch += th; cl += tl;
    }
    g_totH[bh*NOUT + e] = ch;
}

// ================= per-row attention output via binary search =================
__global__ __launch_bounds__(256) void attn_apply_kernel() {
    __shared__ float skey_s[1024];
    int bh = blockIdx.y;
    int b = bh >> 2, h = bh & 3;
    int tid = threadIdx.x;
    int warp = tid >> 5, lane = tid & 31;
    for (int i = tid; i < 1024; i += 256) skey_s[i] = g_skey[bh*ND + i];
    __syncthreads();
    int nbase = blockIdx.x * 128 + warp * 16;
    float tot0 = g_totH[bh*NOUT + lane];
    float tot1 = g_totH[bh*NOUT + lane + 32];
    for (int it = 0; it < 16; it++) {
        int n = nbase + it;
        float sl = g_sl[bh*ND + n];
        float thr = -sl;
        int lo = 0, hi = 1024;
        while (lo < hi) {
            int mid = (lo + hi) >> 1;
            if (skey_s[mid] > thr) hi = mid; else lo = mid + 1;
        }
        int k = lo;
        float esl = __expf(sl);
        float eal = __expf(ALPHA_F * sl);
        float Z = esl * g_zhi[bh*(ND+1) + k] + eal * g_zlo[bh*(ND+1) + k];
        float invZ = 1.0f / Z;
        float ph0 = 0.f, ph1 = 0.f, pl0 = 0.f, pl1 = 0.f;
        if (k > 0) {
            int km = k - 1, sg = km >> 8;
            const float* PH = &g_PH[((size_t)bh*ND + km)*NOUT];
            const float* PL = &g_PL[((size_t)bh*ND + km)*NOUT];
            const float* CH = &g_carrH[(bh*NSEG + sg)*NOUT];
            const float* CL = &g_carrL[(bh*NSEG + sg)*NOUT];
            ph0 = PH[lane]      + CH[lane];
            ph1 = PH[lane + 32] + CH[lane + 32];
            pl0 = PL[lane]      + CL[lane];
            pl1 = PL[lane + 32] + CL[lane + 32];
        }
        float v0 = (esl * (tot0 - ph0) + eal * pl0) * invZ;
        float v1 = (esl * (tot1 - ph1) + eal * pl1) * invZ;
        int orow = (b*ND + n)*NHID + h*NOUT;
        g_hout[orow + lane] = v0;
        g_hout[orow + lane + 32] = v1;
    }
}

// ================= residual + layernorm + bf16 split =================
__device__ float block_sum_256(float v, float* ws) {
    __syncthreads();
    int lane = threadIdx.x & 31, w = threadIdx.x >> 5;
    #pragma unroll
    for (int o = 16; o > 0; o >>= 1) v += __shfl_xor_sync(0xffffffffu, v, o);
    if (lane == 0) ws[w] = v;
    __syncthreads();
    if (threadIdx.x == 0) {
        float s = 0.f;
        #pragma unroll
        for (int i = 0; i < 8; i++) s += ws[i];
        ws[8] = s;
    }
    __syncthreads();
    return ws[8];
}

__global__ __launch_bounds__(256) void ln_kernel(const float* __restrict__ ln_g,
                                                 const float* __restrict__ ln_b, int l) {
    __shared__ float ws[9];
    int row = blockIdx.x, tid = threadIdx.x;
    float v = g_h[row*NHID + tid] + g_hout[row*NHID + tid];
    float mu = block_sum_256(v, ws) * (1.0f / NHID);
    float d = v - mu;
    float var = block_sum_256(d*d, ws) * (1.0f / NHID);
    float o = d * rsqrtf(var + EPS_F) * ln_g[l*NHID + tid] + ln_b[l*NHID + tid];
    g_h[row*NHID + tid] = o;
    __nv_bfloat16 hi = __float2bfloat16(o);
    g_hh[row*NHID + tid] = hi;
    g_hl[row*NHID + tid] = __float2bfloat16(o - __bfloat162float(hi));
}

// ================= launch =================
extern "C" void kernel_launch(void* const* d_in, const int* in_sizes, int n_in,
                              void* d_out, int out_size) {
    const float* X     = (const float*)d_in[0];
    const float* Mk    = (const float*)d_in[1];
    const float* W_in  = (const float*)d_in[2];
    const float* b_in  = (const float*)d_in[3];
    const float* gat_W = (const float*)d_in[4];
    const float* gat_a = (const float*)d_in[5];
    const float* ln_g  = (const float*)d_in[6];
    const float* ln_b  = (const float*)d_in[7];
    const float* W_out = (const float*)d_in[8];
    const float* b_out = (const float*)d_in[9];
    float* out = (float*)d_out;

    cudaFuncSetAttribute(mma_gemm_kernel, cudaFuncAttributeMaxDynamicSharedMemorySize, GSMEM_BYTES);

    __nv_bfloat16 *p_Axh, *p_Axl, *p_WinTh, *p_WinTl, *p_WcatTh, *p_WcatTl, *p_WoutTh, *p_WoutTl, *p_hh, *p_hl;
    float *p_h, *p_hW;
    cudaGetSymbolAddress((void**)&p_Axh, g_Axh);
    cudaGetSymbolAddress((void**)&p_Axl, g_Axl);
    cudaGetSymbolAddress((void**)&p_WinTh, g_WinTh);
    cudaGetSymbolAddress((void**)&p_WinTl, g_WinTl);
    cudaGetSymbolAddress((void**)&p_WcatTh, g_WcatTh);
    cudaGetSymbolAddress((void**)&p_WcatTl, g_WcatTl);
    cudaGetSymbolAddress((void**)&p_WoutTh, g_WoutTh);
    cudaGetSymbolAddress((void**)&p_WoutTl, g_WoutTl);
    cudaGetSymbolAddress((void**)&p_hh, g_hh);
    cudaGetSymbolAddress((void**)&p_hl, g_hl);
    cudaGetSymbolAddress((void**)&p_h, g_h);
    cudaGetSymbolAddress((void**)&p_hW, g_hW);

    posmean_kernel<<<(ND*NT)/256, 256>>>(X, Mk);
    xcat_bf16_kernel<<<(NB*ND*NT)/256, 256>>>(X, Mk);

    // W_in [1024][256] -> WinT [256][1024] (hi/lo)
    transconv_kernel<<<dim3(NHID/32, (2*NT)/32, 1), dim3(32,8)>>>(
        W_in, 2*NT, NHID, p_WinTh, p_WinTl, 2*NT, 0, 0);

    // h = xcat @ W_in + b_in  (M=8192, N=256, K=1024); Alo zero beyond K=512
    mma_gemm_kernel<<<dim3(NHID/128, MR/128), 256, GSMEM_BYTES>>>(
        2*NT, NT, 2*NT, 2*NT, NHID, p_Axh, p_Axl, p_WinTh, p_WinTl, b_in, p_h, p_hh, p_hl);

    for (int l = 0; l < NLAY; l++) {
        // gat_W[l] (h,k,e) -> WcatT[n=h*64+e][k] (hi/lo)
        transconv_kernel<<<dim3(NOUT/32, NHID/32, NHEAD), dim3(32,8)>>>(
            gat_W + (size_t)l*NHEAD*NHID*NOUT, NHID, NOUT,
            p_WcatTh, p_WcatTl, NHID, NOUT, NHID*NOUT);
        // hW = h @ Wcat  (M=8192, N=256, K=256)
        mma_gemm_kernel<<<dim3(NHID/128, MR/128), 256, GSMEM_BYTES>>>(
            NHID, NHID, NHID, NHID, NHID, p_hh, p_hl, p_WcatTh, p_WcatTl, nullptr, p_hW, nullptr, nullptr);
        s_kernel<<<(MR*NHEAD)/256, 256>>>(gat_a, l);
        prep_sort_kernel<<<NBH, 1024>>>();
        prep_scan_kernel<<<dim3(NSEG, NBH), 1024>>>();
        seg_carry_kernel<<<(NBH*NOUT)/256, 256>>>();
        attn_apply_kernel<<<dim3(ND/128, NBH), 256>>>();
        ln_kernel<<<MR, 256>>>(ln_g, ln_b, l);
    }

    // W_out [256][512] -> WoutT [512][256] (hi/lo)
    transconv_kernel<<<dim3(NT/32, NHID/32, 1), dim3(32,8)>>>(
        W_out, NHID, NT, p_WoutTh, p_WoutTl, NHID, 0, 0);
    // out = h @ W_out + b_out  (M=8192, N=512, K=256)
    mma_gemm_kernel<<<dim3(NT/128, MR/128), 256, GSMEM_BYTES>>>(
        NHID, NHID, NHID, NHID, NT, p_hh, p_hl, p_WoutTh, p_WoutTl, b_out, out, nullptr, nullptr);
}